// round 12
// baseline (speedup 1.0000x reference)
#include <cuda_runtime.h>
#include <cuda_bf16.h>
#include <math.h>

typedef unsigned long long ull;
#define DINL __device__ __forceinline__

// ---------------- problem constants ------------------------------------------
#define NE   300      // embedding dim
#define NH2  256      // hidden per direction
#define NT   10       // tags
#define NB   64       // batch
#define NS   256      // seq len
#define NM   16384    // NS*NB rows
#define NG   2048     // 2 * 4 * NH2 gate rows

// ---------------- persistent scratch (__device__ globals, no allocs) ---------
__device__ float    g_XT[NE * NM];          // x^T  [k][m]            19.7 MB
__device__ float    g_WT[NE * NG];          // wih^T combined [k][g]   2.4 MB
__device__ float    g_bias[NG];             // bih + bhh folded
__device__ float    g_xg[(size_t)NG * NM];  // gate inputs [g][m]    134.2 MB
__device__ float    g_h[2][2][NM];          // [dir][buf][(u>>1)*128 + b*2 + (u&1)]
__device__ float    g_hist[2][(size_t)NM * NH2]; // [dir][m*256+u]    33.5 MB
__device__ float    g_feats[NM * NT];
__device__ unsigned g_ctr[2];

// ---------------- f32x2 helpers ----------------------------------------------
union F2U { ull u; float2 f; };
union F4U { float4 f; ull u[2]; };

DINL void fma2(ull &d, ull a, ull b) {
    asm("fma.rn.f32x2 %0, %1, %2, %0;" : "+l"(d) : "l"(a), "l"(b));
}
DINL ull dup2(float x) {
    ull r; asm("mov.b64 %0, {%1, %1};" : "=l"(r) : "f"(x)); return r;
}
DINL float hsum2(ull u) { F2U t; t.u = u; return t.f.x + t.f.y; }
DINL float sigm(float x) { return 1.0f / (1.0f + expf(-x)); }

// ---------------- K0: embedding gather -> g_XT[k][m] -------------------------
__global__ void __launch_bounds__(256) k_gather(const int *__restrict__ sent,
                                                const float *__restrict__ emb) {
    int idx = blockIdx.x * 256 + threadIdx.x;          // 75 float4 per row
    if (idx >= 75 * NM) return;
    int k4 = idx >> 14;            // idx / 16384
    int m  = idx & (NM - 1);
    int tok = sent[m];
    float4 v = *reinterpret_cast<const float4 *>(emb + (size_t)tok * NE + k4 * 4);
    g_XT[(k4 * 4 + 0) * NM + m] = v.x;
    g_XT[(k4 * 4 + 1) * NM + m] = v.y;
    g_XT[(k4 * 4 + 2) * NM + m] = v.z;
    g_XT[(k4 * 4 + 3) * NM + m] = v.w;
}

// ---------------- K0b: wih transpose, bias fold, state init ------------------
__global__ void __launch_bounds__(256) k_prep(const float *wf, const float *wb,
                                              const float *bif, const float *bhf,
                                              const float *bib, const float *bhb,
                                              const float *h0) {
    int idx0 = blockIdx.x * blockDim.x + threadIdx.x;
    int stride = gridDim.x * blockDim.x;
    for (int i = idx0; i < NE * NG; i += stride) {     // i = k*2048 + g
        int k = i >> 11, g = i & (NG - 1);
        g_WT[i] = (g < 1024) ? wf[g * NE + k] : wb[(g - 1024) * NE + k];
    }
    for (int i = idx0; i < NG; i += stride)
        g_bias[i] = (i < 1024) ? bif[i] + bhf[i] : bib[i - 1024] + bhb[i - 1024];
    for (int i = idx0; i < 2 * NB * NH2; i += stride) {
        int dir = i >> 14, r = i & 16383, b = r >> 8, u = r & 255;
        g_h[dir][0][(u >> 1) * 128 + b * 2 + (u & 1)] = h0[i];
    }
    if (idx0 < 2) g_ctr[idx0] = 0u;
}

// ---------------- K1: input GEMM (f32x2) g_xg[g][m] = W x + bias -------------
__global__ void __launch_bounds__(256) k_gemm() {
    __shared__ float Ws[12][64];
    __shared__ float Xs[12][128];
    const int tid = threadIdx.x;
    const int m0 = blockIdx.x * 128;
    const int g0 = blockIdx.y * 64;
    const int tx = tid & 15, ty = tid >> 4;

    ull acc[4][4];
#pragma unroll
    for (int i = 0; i < 4; i++)
#pragma unroll
        for (int j = 0; j < 4; j++) acc[i][j] = 0ull;

    for (int k0 = 0; k0 < NE; k0 += 12) {
        __syncthreads();
        if (tid < 192) {
            int kk = tid >> 4, gp = (tid & 15) * 4;
            *reinterpret_cast<float4 *>(&Ws[kk][gp]) =
                *reinterpret_cast<const float4 *>(&g_WT[(k0 + kk) * NG + g0 + gp]);
        }
        for (int i = tid; i < 384; i += 256) {
            int kk = i >> 5, mp = (i & 31) * 4;
            *reinterpret_cast<float4 *>(&Xs[kk][mp]) =
                *reinterpret_cast<const float4 *>(&g_XT[(k0 + kk) * NM + m0 + mp]);
        }
        __syncthreads();
#pragma unroll
        for (int kk = 0; kk < 12; kk++) {
            float4 w = *reinterpret_cast<float4 *>(&Ws[kk][ty * 4]);
            F4U x0, x1;
            x0.f = *reinterpret_cast<float4 *>(&Xs[kk][tx * 8]);
            x1.f = *reinterpret_cast<float4 *>(&Xs[kk][tx * 8 + 4]);
            ull wp[4] = {dup2(w.x), dup2(w.y), dup2(w.z), dup2(w.w)};
#pragma unroll
            for (int i = 0; i < 4; i++) {
                fma2(acc[i][0], wp[i], x0.u[0]);
                fma2(acc[i][1], wp[i], x0.u[1]);
                fma2(acc[i][2], wp[i], x1.u[0]);
                fma2(acc[i][3], wp[i], x1.u[1]);
            }
        }
    }
#pragma unroll
    for (int i = 0; i < 4; i++) {
        int g = g0 + ty * 4 + i;
        float bv = g_bias[g];
        float *dst = &g_xg[(size_t)g * NM + m0 + tx * 8];
        F2U p0, p1, p2, p3;
        p0.u = acc[i][0]; p1.u = acc[i][1]; p2.u = acc[i][2]; p3.u = acc[i][3];
        float4 o0 = make_float4(p0.f.x + bv, p0.f.y + bv, p1.f.x + bv, p1.f.y + bv);
        float4 o1 = make_float4(p2.f.x + bv, p2.f.y + bv, p3.f.x + bv, p3.f.y + bv);
        *reinterpret_cast<float4 *>(dst) = o0;
        *reinterpret_cast<float4 *>(dst + 4) = o1;
    }
}

// ---------------- K2: persistent bidirectional LSTM recurrence ---------------
// 128 CTAs x 128 threads: dir = bid>>6; gb = bid&63 owns h-units [gb*4, gb*4+4).
// Each thread: 1 h-unit (ul = tid>>5) x 2 adjacent batches (bp2 = tid&31).
// One LDS.128 of h feeds 2 batches x 2 k; broadcast w wavefronts halve vs 8 warps.
__global__ void __launch_bounds__(128) k_lstm(const float *__restrict__ whh_f,
                                              const float *__restrict__ whh_b,
                                              const float *__restrict__ c0) {
    extern __shared__ float sm[];
    float *whh_sh = sm;             // [16][256]  16 KB
    float *h_sh   = sm + 16 * 256;  // [(u>>1)*128 + b*2 + (u&1)]  64 KB

    const int tid = threadIdx.x;
    const int dir = blockIdx.x >> 6;
    const int gb  = blockIdx.x & 63;
    const int ul  = tid >> 5;           // 0..3  (warp id; uniform per warp)
    const int bp2 = tid & 31;           // batch pair 0..31
    const int b0  = bp2 * 2;            // batches b0, b0+1
    const int hu  = gb * 4 + ul;        // global h-unit
    const float *whh = dir ? whh_b : whh_f;

    // load whh slice: local row lr = gate*4 + u2  <-  global row gate*256 + gb*4 + u2
    for (int i = tid; i < 16 * 64; i += 128) {
        int lr = i >> 6, q = i & 63;
        int gate = lr >> 2, u2 = lr & 3;
        *reinterpret_cast<float4 *>(&whh_sh[lr * 256 + q * 4]) =
            *reinterpret_cast<const float4 *>(&whh[(gate * 256 + gb * 4 + u2) * 256 + q * 4]);
    }

    float ca = c0[dir * (NB * NH2) + b0 * 256 + hu];
    float cb = c0[dir * (NB * NH2) + (b0 + 1) * 256 + hu];

    const float *w0 = whh_sh + (0 * 4 + ul) * 256;   // i
    const float *w1 = whh_sh + (1 * 4 + ul) * 256;   // f
    const float *w2 = whh_sh + (2 * 4 + ul) * 256;   // g
    const float *w3 = whh_sh + (3 * 4 + ul) * 256;   // o
    unsigned *ctr = &g_ctr[dir];

    for (int t = 0; t < NS; t++) {
        const int tt = dir ? (NS - 1 - t) : t;

        // copy h (16384 floats) from L2-coherent buffer into smem
        const float4 *hsrc = reinterpret_cast<const float4 *>(g_h[dir][t & 1]);
        float4 *hdst = reinterpret_cast<float4 *>(h_sh);
        for (int i = tid; i < 4096; i += 128) hdst[i] = __ldcg(hsrc + i);
        __syncthreads();

        // 8 accumulators: [gate][batch of pair]
        ull a00 = 0, a01 = 0, a10 = 0, a11 = 0, a20 = 0, a21 = 0, a30 = 0, a31 = 0;
#pragma unroll 4
        for (int j = 0; j < 128; j += 2) {          // covers k = 2j .. 2j+3
            F4U h0q, h1q;
            h0q.f = *reinterpret_cast<const float4 *>(&h_sh[j * 128 + bp2 * 4]);
            h1q.f = *reinterpret_cast<const float4 *>(&h_sh[(j + 1) * 128 + bp2 * 4]);
            // h0q.u[0] = (h[2j][b0],   h[2j+1][b0]);  h0q.u[1] = (h[2j][b1],   h[2j+1][b1])
            // h1q.u[0] = (h[2j+2][b0], h[2j+3][b0]);  h1q.u[1] = (h[2j+2][b1], h[2j+3][b1])
            F4U q0, q1, q2, q3;
            q0.f = *reinterpret_cast<const float4 *>(&w0[j * 2]);
            q1.f = *reinterpret_cast<const float4 *>(&w1[j * 2]);
            q2.f = *reinterpret_cast<const float4 *>(&w2[j * 2]);
            q3.f = *reinterpret_cast<const float4 *>(&w3[j * 2]);
            fma2(a00, q0.u[0], h0q.u[0]); fma2(a01, q0.u[0], h0q.u[1]);
            fma2(a00, q0.u[1], h1q.u[0]); fma2(a01, q0.u[1], h1q.u[1]);
            fma2(a10, q1.u[0], h0q.u[0]); fma2(a11, q1.u[0], h0q.u[1]);
            fma2(a10, q1.u[1], h1q.u[0]); fma2(a11, q1.u[1], h1q.u[1]);
            fma2(a20, q2.u[0], h0q.u[0]); fma2(a21, q2.u[0], h0q.u[1]);
            fma2(a20, q2.u[1], h1q.u[0]); fma2(a21, q2.u[1], h1q.u[1]);
            fma2(a30, q3.u[0], h0q.u[0]); fma2(a31, q3.u[0], h0q.u[1]);
            fma2(a30, q3.u[1], h1q.u[0]); fma2(a31, q3.u[1], h1q.u[1]);
        }

        const int col = tt * 64 + b0;               // even -> 8B aligned
        const int gofs = dir * 1024 + hu;
        float2 xi = *reinterpret_cast<const float2 *>(&g_xg[(size_t)(gofs + 0 * 256) * NM + col]);
        float2 xf = *reinterpret_cast<const float2 *>(&g_xg[(size_t)(gofs + 1 * 256) * NM + col]);
        float2 xc = *reinterpret_cast<const float2 *>(&g_xg[(size_t)(gofs + 2 * 256) * NM + col]);
        float2 xo = *reinterpret_cast<const float2 *>(&g_xg[(size_t)(gofs + 3 * 256) * NM + col]);

        float iga = sigm(xi.x + hsum2(a00)), igb = sigm(xi.y + hsum2(a01));
        float fga = sigm(xf.x + hsum2(a10)), fgb = sigm(xf.y + hsum2(a11));
        float gga = tanhf(xc.x + hsum2(a20)), ggb = tanhf(xc.y + hsum2(a21));
        float oga = sigm(xo.x + hsum2(a30)), ogb = sigm(xo.y + hsum2(a31));
        ca = fga * ca + iga * gga;
        cb = fgb * cb + igb * ggb;
        float ha = oga * tanhf(ca);
        float hb = ogb * tanhf(cb);

        float *hout = g_h[dir][(t + 1) & 1];
        __stcg(&hout[(hu >> 1) * 128 + b0 * 2 + (hu & 1)], ha);
        __stcg(&hout[(hu >> 1) * 128 + (b0 + 1) * 2 + (hu & 1)], hb);
        g_hist[dir][(size_t)(tt * 64 + b0) * 256 + hu] = ha;
        g_hist[dir][(size_t)(tt * 64 + b0 + 1) * 256 + hu] = hb;

        // per-direction grid barrier (monotonic counter)
        __syncthreads();
        if (tid == 0) {
            __threadfence();
            atomicAdd(ctr, 1u);
            const unsigned target = 64u * (unsigned)(t + 1);
            while (*reinterpret_cast<volatile unsigned *>(ctr) < target) { }
            __threadfence();
        }
        __syncthreads();
    }
}

// ---------------- K3: feature GEMM (16384 x 10 x 512) ------------------------
__global__ void __launch_bounds__(256) k_feats(const float *__restrict__ Wout,
                                               const float *__restrict__ bout) {
    __shared__ float ws[NT][512];
    __shared__ float bs[NT];
    const int tid = threadIdx.x;
    for (int i = tid; i < NT * 512; i += 256) ws[i >> 9][i & 511] = Wout[i];
    if (tid < NT) bs[tid] = bout[tid];
    __syncthreads();

    const int m = blockIdx.x * 256 + tid;
    float acc[NT];
#pragma unroll
    for (int tg = 0; tg < NT; tg++) acc[tg] = bs[tg];

    const float4 *hf = reinterpret_cast<const float4 *>(&g_hist[0][(size_t)m * 256]);
    const float4 *hb = reinterpret_cast<const float4 *>(&g_hist[1][(size_t)m * 256]);
#pragma unroll 4
    for (int k4 = 0; k4 < 64; k4++) {
        float4 a = hf[k4];
#pragma unroll
        for (int tg = 0; tg < NT; tg++) {
            float4 w = *reinterpret_cast<float4 *>(&ws[tg][k4 * 4]);
            acc[tg] += a.x * w.x + a.y * w.y + a.z * w.z + a.w * w.w;
        }
    }
#pragma unroll 4
    for (int k4 = 0; k4 < 64; k4++) {
        float4 a = hb[k4];
#pragma unroll
        for (int tg = 0; tg < NT; tg++) {
            float4 w = *reinterpret_cast<float4 *>(&ws[tg][256 + k4 * 4]);
            acc[tg] += a.x * w.x + a.y * w.y + a.z * w.z + a.w * w.w;
        }
    }
#pragma unroll
    for (int tg = 0; tg < NT; tg++) g_feats[m * NT + tg] = acc[tg];
}

// ---------------- K4: Viterbi (1 warp per batch) -----------------------------
__global__ void __launch_bounds__(32) k_viterbi(const float *__restrict__ trans,
                                                float *__restrict__ out, int out_size) {
    __shared__ int   bp[NS][NT];
    __shared__ float fs[NS][NT];
    const int b = blockIdx.x;
    const int lane = threadIdx.x;
    const bool act = lane < NT;

    for (int i = lane; i < NS * NT; i += 32)
        (&fs[0][0])[i] = g_feats[b * NS * NT + i];

    float tr[NT];
#pragma unroll
    for (int p = 0; p < NT; p++) tr[p] = 0.0f;
    if (act)
#pragma unroll
        for (int p = 0; p < NT; p++) tr[p] = trans[lane * NT + p];

    float fv = act ? (lane == 8 ? 0.0f : -10000.0f) : -1e30f;
    __syncwarp();

    for (int s = 0; s < NS; s++) {
        float best = -1e30f; int bpi = 0;
#pragma unroll
        for (int p = 0; p < NT; p++) {
            float fvp = __shfl_sync(0xffffffffu, fv, p);
            float v = fvp + tr[p];
            if (v > best) { best = v; bpi = p; }   // strict > keeps lowest index
        }
        if (act) {
            bp[s][lane] = bpi;
            fv = best + fs[s][lane];
        }
        __syncwarp();
    }
    float term = act ? fv + trans[9 * NT + lane] : -1e30f;

    float bestt = -1e30f; int bi = 0;
#pragma unroll
    for (int p = 0; p < NT; p++) {
        float v = __shfl_sync(0xffffffffu, term, p);
        if (v > bestt) { bestt = v; bi = p; }
    }
    __syncwarp();

    if (lane == 0) {
        if (b < out_size) out[b] = bestt;
        int cur = bi;
        const int base = NB + b * NS;
        if (base + NS - 1 < out_size) out[base + NS - 1] = (float)cur;
        for (int s = NS - 2; s >= 0; s--) {
            cur = bp[s + 1][cur];
            if (base + s < out_size) out[base + s] = (float)cur;
        }
    }
}

// ---------------- host launcher ----------------------------------------------
extern "C" void kernel_launch(void* const* d_in, const int* in_sizes, int n_in,
                              void* d_out, int out_size) {
    const int *sent = nullptr;
    const float *emb = nullptr, *Wout = nullptr, *bout = nullptr;
    const float *h0 = nullptr, *c0 = nullptr, *trans = nullptr;
    const float *wih[2] = {nullptr, nullptr}, *whh[2] = {nullptr, nullptr};
    const float *bb[4]  = {nullptr, nullptr, nullptr, nullptr};
    int nwih = 0, nwhh = 0, nb = 0, nhc = 0;

    for (int i = 0; i < n_in; i++) {
        const void *p = d_in[i];
        switch (in_sizes[i]) {
            case 16384:    sent = (const int *)p; break;
            case 15000000: emb = (const float *)p; break;
            case 307200:   if (nwih < 2) wih[nwih++] = (const float *)p; break;
            case 262144:   if (nwhh < 2) whh[nwhh++] = (const float *)p; break;
            case 1024:     if (nb < 4) bb[nb++] = (const float *)p; break;
            case 5120:     Wout = (const float *)p; break;
            case 10:       bout = (const float *)p; break;
            case 32768:    if (nhc == 0) h0 = (const float *)p; else c0 = (const float *)p; nhc++; break;
            case 100:      trans = (const float *)p; break;
            default: break;
        }
    }

    // k_lstm needs 80 KB dynamic smem; attribute set is idempotent & capture-safe
    cudaFuncSetAttribute(k_lstm, cudaFuncAttributeMaxDynamicSharedMemorySize, 96 * 1024);

    k_gather<<<(75 * NM + 255) / 256, 256>>>(sent, emb);
    k_prep<<<512, 256>>>(wih[0], wih[1], bb[0], bb[1], bb[2], bb[3], h0);
    k_gemm<<<dim3(NM / 128, NG / 64), 256>>>();
    k_lstm<<<128, 128, (16 * 256 + 64 * 256) * sizeof(float)>>>(whh[0], whh[1], c0);
    k_feats<<<NM / 256, 256>>>(Wout, bout);
    k_viterbi<<<NB, 32>>>(trans, (float *)d_out, out_size);
}

// round 15
// speedup vs baseline: 1.2205x; 1.2205x over previous
#include <cuda_runtime.h>
#include <cuda_bf16.h>
#include <math.h>

typedef unsigned long long ull;
#define DINL __device__ __forceinline__

// ---------------- problem constants ------------------------------------------
#define NE   300      // embedding dim
#define NH2  256      // hidden per direction
#define NT   10       // tags
#define NB   64       // batch
#define NS   256      // seq len
#define NM   16384    // NS*NB rows
#define NG   2048     // 2 * 4 * NH2 gate rows

// ---------------- persistent scratch (__device__ globals, no allocs) ---------
__device__ float    g_XT[NE * NM];          // x^T  [k][m]            19.7 MB
__device__ float    g_WT[NE * NG];          // wih^T combined [k][g]   2.4 MB
__device__ float    g_bias[NG];             // bih + bhh folded
__device__ float    g_xg[(size_t)NG * NM];  // gate inputs [g][m]    134.2 MB
__device__ float    g_h[2][2][NM];          // [dir][buf][(u>>1)*128 + b*2 + (u&1)]
__device__ float    g_hist[2][(size_t)NM * NH2]; // [dir][m*256+u]    33.5 MB
__device__ float    g_feats[NM * NT];
__device__ unsigned g_ctr[2];

// ---------------- f32x2 helpers ----------------------------------------------
union F2U { ull u; float2 f; };
union F4U { float4 f; ull u[2]; };

DINL void fma2(ull &d, ull a, ull b) {
    asm("fma.rn.f32x2 %0, %1, %2, %0;" : "+l"(d) : "l"(a), "l"(b));
}
DINL void add2(ull &d, ull a) {
    asm("add.rn.f32x2 %0, %0, %1;" : "+l"(d) : "l"(a));
}
DINL ull dup2(float x) {
    ull r; asm("mov.b64 %0, {%1, %1};" : "=l"(r) : "f"(x)); return r;
}
DINL float hsum2(ull u) { F2U t; t.u = u; return t.f.x + t.f.y; }
// fast, accurate-enough gates (err ~1e-6; rel_err margin is 1e-3)
DINL float fsigm(float x) { return __fdividef(1.0f, 1.0f + __expf(-x)); }
DINL float ftanh(float x) { return 1.0f - __fdividef(2.0f, __expf(2.0f * x) + 1.0f); }

// ---------------- K0: embedding gather -> g_XT[k][m] -------------------------
__global__ void __launch_bounds__(256) k_gather(const int *__restrict__ sent,
                                                const float *__restrict__ emb) {
    int idx = blockIdx.x * 256 + threadIdx.x;          // 75 float4 per row
    if (idx >= 75 * NM) return;
    int k4 = idx >> 14;            // idx / 16384
    int m  = idx & (NM - 1);
    int tok = sent[m];
    float4 v = *reinterpret_cast<const float4 *>(emb + (size_t)tok * NE + k4 * 4);
    g_XT[(k4 * 4 + 0) * NM + m] = v.x;
    g_XT[(k4 * 4 + 1) * NM + m] = v.y;
    g_XT[(k4 * 4 + 2) * NM + m] = v.z;
    g_XT[(k4 * 4 + 3) * NM + m] = v.w;
}

// ---------------- K0b: wih transpose, bias fold, state init ------------------
__global__ void __launch_bounds__(256) k_prep(const float *wf, const float *wb,
                                              const float *bif, const float *bhf,
                                              const float *bib, const float *bhb,
                                              const float *h0) {
    int idx0 = blockIdx.x * blockDim.x + threadIdx.x;
    int stride = gridDim.x * blockDim.x;
    for (int i = idx0; i < NE * NG; i += stride) {     // i = k*2048 + g
        int k = i >> 11, g = i & (NG - 1);
        g_WT[i] = (g < 1024) ? wf[g * NE + k] : wb[(g - 1024) * NE + k];
    }
    for (int i = idx0; i < NG; i += stride)
        g_bias[i] = (i < 1024) ? bif[i] + bhf[i] : bib[i - 1024] + bhb[i - 1024];
    for (int i = idx0; i < 2 * NB * NH2; i += stride) {
        int dir = i >> 14, r = i & 16383, b = r >> 8, u = r & 255;
        g_h[dir][0][(u >> 1) * 128 + b * 2 + (u & 1)] = h0[i];
    }
    if (idx0 < 2) g_ctr[idx0] = 0u;
}

// ---------------- K1: input GEMM (f32x2) g_xg[g][m] = W x + bias -------------
__global__ void __launch_bounds__(256) k_gemm() {
    __shared__ float Ws[12][64];
    __shared__ float Xs[12][128];
    const int tid = threadIdx.x;
    const int m0 = blockIdx.x * 128;
    const int g0 = blockIdx.y * 64;
    const int tx = tid & 15, ty = tid >> 4;

    ull acc[4][4];
#pragma unroll
    for (int i = 0; i < 4; i++)
#pragma unroll
        for (int j = 0; j < 4; j++) acc[i][j] = 0ull;

    for (int k0 = 0; k0 < NE; k0 += 12) {
        __syncthreads();
        if (tid < 192) {
            int kk = tid >> 4, gp = (tid & 15) * 4;
            *reinterpret_cast<float4 *>(&Ws[kk][gp]) =
                *reinterpret_cast<const float4 *>(&g_WT[(k0 + kk) * NG + g0 + gp]);
        }
        for (int i = tid; i < 384; i += 256) {
            int kk = i >> 5, mp = (i & 31) * 4;
            *reinterpret_cast<float4 *>(&Xs[kk][mp]) =
                *reinterpret_cast<const float4 *>(&g_XT[(k0 + kk) * NM + m0 + mp]);
        }
        __syncthreads();
#pragma unroll
        for (int kk = 0; kk < 12; kk++) {
            float4 w = *reinterpret_cast<float4 *>(&Ws[kk][ty * 4]);
            F4U x0, x1;
            x0.f = *reinterpret_cast<float4 *>(&Xs[kk][tx * 8]);
            x1.f = *reinterpret_cast<float4 *>(&Xs[kk][tx * 8 + 4]);
            ull wp[4] = {dup2(w.x), dup2(w.y), dup2(w.z), dup2(w.w)};
#pragma unroll
            for (int i = 0; i < 4; i++) {
                fma2(acc[i][0], wp[i], x0.u[0]);
                fma2(acc[i][1], wp[i], x0.u[1]);
                fma2(acc[i][2], wp[i], x1.u[0]);
                fma2(acc[i][3], wp[i], x1.u[1]);
            }
        }
    }
#pragma unroll
    for (int i = 0; i < 4; i++) {
        int g = g0 + ty * 4 + i;
        float bv = g_bias[g];
        float *dst = &g_xg[(size_t)g * NM + m0 + tx * 8];
        F2U p0, p1, p2, p3;
        p0.u = acc[i][0]; p1.u = acc[i][1]; p2.u = acc[i][2]; p3.u = acc[i][3];
        float4 o0 = make_float4(p0.f.x + bv, p0.f.y + bv, p1.f.x + bv, p1.f.y + bv);
        float4 o1 = make_float4(p2.f.x + bv, p2.f.y + bv, p3.f.x + bv, p3.f.y + bv);
        *reinterpret_cast<float4 *>(dst) = o0;
        *reinterpret_cast<float4 *>(dst + 4) = o1;
    }
}

// ---------------- K2: persistent bidirectional LSTM recurrence ---------------
// 128 CTAs x 256 threads (8 warps). dir = bid>>6; gb = bid&63 owns h-units
// [gb*4, gb*4+4). Warp wid: ul = wid>>1 (h-unit), kh = wid&1 (k-half).
// Thread: 1 h-unit x 2 adjacent batches x half the k-range (32 dot iters).
// Partials combined across the warp pair through an 8KB smem exchange (f32x2
// adds). 8 warps double latency hiding vs R12's 4 (measured occ 6.2%, issue
// 13.8% -> latency-exposed, not throughput-bound).
__global__ void __launch_bounds__(256) k_lstm(const float *__restrict__ whh_f,
                                              const float *__restrict__ whh_b,
                                              const float *__restrict__ c0) {
    extern __shared__ float sm[];
    float *whh_sh = sm;                       // [16][256]  16 KB
    float *h_sh   = sm + 16 * 256;            // 16384 floats, 64 KB
    ull   *red    = (ull *)(sm + 16 * 256 + NM); // [8 acc][4 ul][32 lane]  8 KB

    const int tid = threadIdx.x;
    const int dir = blockIdx.x >> 6;
    const int gb  = blockIdx.x & 63;
    const int wid = tid >> 5;
    const int ul  = wid >> 1;           // 0..3  h-unit within CTA (uniform/warp)
    const int kh  = wid & 1;            // 0..1  k-half (uniform/warp)
    const int lane = tid & 31;
    const int b0  = lane * 2;           // batches b0, b0+1
    const int hu  = gb * 4 + ul;        // global h-unit
    const float *whh = dir ? whh_b : whh_f;

    // load whh slice: local row lr = gate*4 + u2  <-  global row gate*256 + gb*4 + u2
    for (int i = tid; i < 16 * 64; i += 256) {
        int lr = i >> 6, q = i & 63;
        int gate = lr >> 2, u2 = lr & 3;
        *reinterpret_cast<float4 *>(&whh_sh[lr * 256 + q * 4]) =
            *reinterpret_cast<const float4 *>(&whh[(gate * 256 + gb * 4 + u2) * 256 + q * 4]);
    }

    float ca = c0[dir * (NB * NH2) + b0 * 256 + hu];
    float cb = c0[dir * (NB * NH2) + (b0 + 1) * 256 + hu];

    const float *w0 = whh_sh + (0 * 4 + ul) * 256;   // i
    const float *w1 = whh_sh + (1 * 4 + ul) * 256;   // f
    const float *w2 = whh_sh + (2 * 4 + ul) * 256;   // g
    const float *w3 = whh_sh + (3 * 4 + ul) * 256;   // o
    const int jbase = kh * 64;          // this warp's k-pair range [jbase, jbase+64)
    unsigned *ctr = &g_ctr[dir];

    for (int t = 0; t < NS; t++) {
        const int tt = dir ? (NS - 1 - t) : t;

        // copy h (16384 floats) from L2-coherent buffer into smem (16/thread)
        const float4 *hsrc = reinterpret_cast<const float4 *>(g_h[dir][t & 1]);
        float4 *hdst = reinterpret_cast<float4 *>(h_sh);
        for (int i = tid; i < 4096; i += 256) hdst[i] = __ldcg(hsrc + i);

        // prefetch gate inputs early (independent of h) — kh==0 warps only
        float2 xi, xf, xc, xo;
        if (kh == 0) {
            const int col = tt * 64 + b0;
            const int gofs = dir * 1024 + hu;
            xi = *reinterpret_cast<const float2 *>(&g_xg[(size_t)(gofs + 0 * 256) * NM + col]);
            xf = *reinterpret_cast<const float2 *>(&g_xg[(size_t)(gofs + 1 * 256) * NM + col]);
            xc = *reinterpret_cast<const float2 *>(&g_xg[(size_t)(gofs + 2 * 256) * NM + col]);
            xo = *reinterpret_cast<const float2 *>(&g_xg[(size_t)(gofs + 3 * 256) * NM + col]);
        }
        __syncthreads();

        // half-k dot: 32 iterations covering k in [kh*128, kh*128+128)
        ull a00 = 0, a01 = 0, a10 = 0, a11 = 0, a20 = 0, a21 = 0, a30 = 0, a31 = 0;
#pragma unroll 8
        for (int jj = 0; jj < 64; jj += 2) {
            const int j = jbase + jj;               // k-pair index; covers k=2j..2j+3
            F4U h0q, h1q;
            h0q.f = *reinterpret_cast<const float4 *>(&h_sh[j * 128 + lane * 4]);
            h1q.f = *reinterpret_cast<const float4 *>(&h_sh[(j + 1) * 128 + lane * 4]);
            // h0q.u[0]=(h[2j][b0],h[2j+1][b0])  h0q.u[1]=(h[2j][b1],h[2j+1][b1])
            // h1q.u[0]=(h[2j+2][b0],h[2j+3][b0]) h1q.u[1]=(h[2j+2][b1],h[2j+3][b1])
            F4U q0, q1, q2, q3;
            q0.f = *reinterpret_cast<const float4 *>(&w0[j * 2]);
            q1.f = *reinterpret_cast<const float4 *>(&w1[j * 2]);
            q2.f = *reinterpret_cast<const float4 *>(&w2[j * 2]);
            q3.f = *reinterpret_cast<const float4 *>(&w3[j * 2]);
            fma2(a00, q0.u[0], h0q.u[0]); fma2(a01, q0.u[0], h0q.u[1]);
            fma2(a00, q0.u[1], h1q.u[0]); fma2(a01, q0.u[1], h1q.u[1]);
            fma2(a10, q1.u[0], h0q.u[0]); fma2(a11, q1.u[0], h0q.u[1]);
            fma2(a10, q1.u[1], h1q.u[0]); fma2(a11, q1.u[1], h1q.u[1]);
            fma2(a20, q2.u[0], h0q.u[0]); fma2(a21, q2.u[0], h0q.u[1]);
            fma2(a20, q2.u[1], h1q.u[0]); fma2(a21, q2.u[1], h1q.u[1]);
            fma2(a30, q3.u[0], h0q.u[0]); fma2(a31, q3.u[0], h0q.u[1]);
            fma2(a30, q3.u[1], h1q.u[0]); fma2(a31, q3.u[1], h1q.u[1]);
        }

        // kh==1 warps publish partials: red[(acc*4 + ul)*32 + lane] (conflict-free)
        if (kh == 1) {
            red[(0 * 4 + ul) * 32 + lane] = a00;
            red[(1 * 4 + ul) * 32 + lane] = a01;
            red[(2 * 4 + ul) * 32 + lane] = a10;
            red[(3 * 4 + ul) * 32 + lane] = a11;
            red[(4 * 4 + ul) * 32 + lane] = a20;
            red[(5 * 4 + ul) * 32 + lane] = a21;
            red[(6 * 4 + ul) * 32 + lane] = a30;
            red[(7 * 4 + ul) * 32 + lane] = a31;
        }
        __syncthreads();

        float ha = 0.0f, hb = 0.0f;
        if (kh == 0) {
            add2(a00, red[(0 * 4 + ul) * 32 + lane]);
            add2(a01, red[(1 * 4 + ul) * 32 + lane]);
            add2(a10, red[(2 * 4 + ul) * 32 + lane]);
            add2(a11, red[(3 * 4 + ul) * 32 + lane]);
            add2(a20, red[(4 * 4 + ul) * 32 + lane]);
            add2(a21, red[(5 * 4 + ul) * 32 + lane]);
            add2(a30, red[(6 * 4 + ul) * 32 + lane]);
            add2(a31, red[(7 * 4 + ul) * 32 + lane]);

            float iga = fsigm(xi.x + hsum2(a00)), igb = fsigm(xi.y + hsum2(a01));
            float fga = fsigm(xf.x + hsum2(a10)), fgb = fsigm(xf.y + hsum2(a11));
            float gga = ftanh(xc.x + hsum2(a20)), ggb = ftanh(xc.y + hsum2(a21));
            float oga = fsigm(xo.x + hsum2(a30)), ogb = fsigm(xo.y + hsum2(a31));
            ca = fga * ca + iga * gga;
            cb = fgb * cb + igb * ggb;
            ha = oga * ftanh(ca);
            hb = ogb * ftanh(cb);

            float *hout = g_h[dir][(t + 1) & 1];
            __stcg(&hout[(hu >> 1) * 128 + b0 * 2 + (hu & 1)], ha);
            __stcg(&hout[(hu >> 1) * 128 + (b0 + 1) * 2 + (hu & 1)], hb);
        }

        // grid barrier: arrive as soon as h-writes are CTA-complete; overlap the
        // g_hist stores with the spin.
        __syncthreads();
        if (tid == 0) {
            __threadfence();
            atomicAdd(ctr, 1u);
        }
        if (kh == 0) {
            g_hist[dir][(size_t)(tt * 64 + b0) * 256 + hu] = ha;
            g_hist[dir][(size_t)(tt * 64 + b0 + 1) * 256 + hu] = hb;
        }
        if (tid == 0) {
            const unsigned target = 64u * (unsigned)(t + 1);
            while (*reinterpret_cast<volatile unsigned *>(ctr) < target) { }
            __threadfence();
        }
        __syncthreads();
    }
}

// ---------------- K3: feature GEMM (16384 x 10 x 512) ------------------------
__global__ void __launch_bounds__(256) k_feats(const float *__restrict__ Wout,
                                               const float *__restrict__ bout) {
    __shared__ float ws[NT][512];
    __shared__ float bs[NT];
    const int tid = threadIdx.x;
    for (int i = tid; i < NT * 512; i += 256) ws[i >> 9][i & 511] = Wout[i];
    if (tid < NT) bs[tid] = bout[tid];
    __syncthreads();

    const int m = blockIdx.x * 256 + tid;
    float acc[NT];
#pragma unroll
    for (int tg = 0; tg < NT; tg++) acc[tg] = bs[tg];

    const float4 *hf = reinterpret_cast<const float4 *>(&g_hist[0][(size_t)m * 256]);
    const float4 *hb = reinterpret_cast<const float4 *>(&g_hist[1][(size_t)m * 256]);
#pragma unroll 4
    for (int k4 = 0; k4 < 64; k4++) {
        float4 a = hf[k4];
#pragma unroll
        for (int tg = 0; tg < NT; tg++) {
            float4 w = *reinterpret_cast<float4 *>(&ws[tg][k4 * 4]);
            acc[tg] += a.x * w.x + a.y * w.y + a.z * w.z + a.w * w.w;
        }
    }
#pragma unroll 4
    for (int k4 = 0; k4 < 64; k4++) {
        float4 a = hb[k4];
#pragma unroll
        for (int tg = 0; tg < NT; tg++) {
            float4 w = *reinterpret_cast<float4 *>(&ws[tg][256 + k4 * 4]);
            acc[tg] += a.x * w.x + a.y * w.y + a.z * w.z + a.w * w.w;
        }
    }
#pragma unroll
    for (int tg = 0; tg < NT; tg++) g_feats[m * NT + tg] = acc[tg];
}

// ---------------- K4: Viterbi (1 warp per batch) -----------------------------
__global__ void __launch_bounds__(32) k_viterbi(const float *__restrict__ trans,
                                                float *__restrict__ out, int out_size) {
    __shared__ int   bp[NS][NT];
    __shared__ float fs[NS][NT];
    const int b = blockIdx.x;
    const int lane = threadIdx.x;
    const bool act = lane < NT;

    for (int i = lane; i < NS * NT; i += 32)
        (&fs[0][0])[i] = g_feats[b * NS * NT + i];

    float tr[NT];
#pragma unroll
    for (int p = 0; p < NT; p++) tr[p] = 0.0f;
    if (act)
#pragma unroll
        for (int p = 0; p < NT; p++) tr[p] = trans[lane * NT + p];

    float fv = act ? (lane == 8 ? 0.0f : -10000.0f) : -1e30f;
    __syncwarp();

    for (int s = 0; s < NS; s++) {
        float best = -1e30f; int bpi = 0;
#pragma unroll
        for (int p = 0; p < NT; p++) {
            float fvp = __shfl_sync(0xffffffffu, fv, p);
            float v = fvp + tr[p];
            if (v > best) { best = v; bpi = p; }   // strict > keeps lowest index
        }
        if (act) {
            bp[s][lane] = bpi;
            fv = best + fs[s][lane];
        }
        __syncwarp();
    }
    float term = act ? fv + trans[9 * NT + lane] : -1e30f;

    float bestt = -1e30f; int bi = 0;
#pragma unroll
    for (int p = 0; p < NT; p++) {
        float v = __shfl_sync(0xffffffffu, term, p);
        if (v > bestt) { bestt = v; bi = p; }
    }
    __syncwarp();

    if (lane == 0) {
        if (b < out_size) out[b] = bestt;
        int cur = bi;
        const int base = NB + b * NS;
        if (base + NS - 1 < out_size) out[base + NS - 1] = (float)cur;
        for (int s = NS - 2; s >= 0; s--) {
            cur = bp[s + 1][cur];
            if (base + s < out_size) out[base + s] = (float)cur;
        }
    }
}

// ---------------- host launcher ----------------------------------------------
extern "C" void kernel_launch(void* const* d_in, const int* in_sizes, int n_in,
                              void* d_out, int out_size) {
    const int *sent = nullptr;
    const float *emb = nullptr, *Wout = nullptr, *bout = nullptr;
    const float *h0 = nullptr, *c0 = nullptr, *trans = nullptr;
    const float *wih[2] = {nullptr, nullptr}, *whh[2] = {nullptr, nullptr};
    const float *bb[4]  = {nullptr, nullptr, nullptr, nullptr};
    int nwih = 0, nwhh = 0, nb = 0, nhc = 0;

    for (int i = 0; i < n_in; i++) {
        const void *p = d_in[i];
        switch (in_sizes[i]) {
            case 16384:    sent = (const int *)p; break;
            case 15000000: emb = (const float *)p; break;
            case 307200:   if (nwih < 2) wih[nwih++] = (const float *)p; break;
            case 262144:   if (nwhh < 2) whh[nwhh++] = (const float *)p; break;
            case 1024:     if (nb < 4) bb[nb++] = (const float *)p; break;
            case 5120:     Wout = (const float *)p; break;
            case 10:       bout = (const float *)p; break;
            case 32768:    if (nhc == 0) h0 = (const float *)p; else c0 = (const float *)p; nhc++; break;
            case 100:      trans = (const float *)p; break;
            default: break;
        }
    }

    // k_lstm needs 88 KB dynamic smem (16K whh + 64K h + 8K reduce)
    cudaFuncSetAttribute(k_lstm, cudaFuncAttributeMaxDynamicSharedMemorySize, 96 * 1024);

    const int lstm_smem = (16 * 256 + NM) * sizeof(float) + 1024 * sizeof(ull);

    k_gather<<<(75 * NM + 255) / 256, 256>>>(sent, emb);
    k_prep<<<512, 256>>>(wih[0], wih[1], bb[0], bb[1], bb[2], bb[3], h0);
    k_gemm<<<dim3(NM / 128, NG / 64), 256>>>();
    k_lstm<<<128, 256, lstm_smem>>>(whh[0], whh[1], c0);
    k_feats<<<NM / 256, 256>>>(Wout, bout);
    k_viterbi<<<NB, 32>>>(trans, (float *)d_out, out_size);
}